// round 13
// baseline (speedup 1.0000x reference)
#include <cuda_runtime.h>
#include <math.h>
#include <float.h>

#define B 8
#define H 480
#define W 640
#define HW (H*W)
#define TOPK 500
#define NKP (B*TOPK)
#define CAP 131072

#define KXY_OFF 0
#define DESC_OFF (NKP*2)
#define KPS_OFF (DESC_OFF + NKP*64)
#define DISP_OFF (KPS_OFF + NKP)

typedef unsigned long long ull;

// ---------------- device scratch ----------------
__device__ float g_cval[B*CAP];
__device__ int   g_cidx[B*CAP];
__device__ int   g_cnt[B];          // zero at load; re-zeroed by select (replay-safe)
__device__ int   g_topk[NKP];

// ============================================================================
// Fused NMS: 32-wide x 120-tall output tile, radius-10 halo -> 140 rows x 56
// padded cols (sc in [2,54)). Halo overhead 1.90x (vs 2.64x for 32x32).
// Same proven phase structure as the 37.7us kernel: float4 smem passes,
// masks bit-packed one ull per row.
// ============================================================================
#define WP 56
#define TR 140   /* tile rows */

__device__ __forceinline__ float4 f4max(float4 a, float4 b) {
    return make_float4(fmaxf(a.x,b.x), fmaxf(a.y,b.y), fmaxf(a.z,b.z), fmaxf(a.w,b.w));
}
__device__ __forceinline__ float fmax5(float a, float b, float c, float d, float e) {
    return fmaxf(fmaxf(fmaxf(a, b), fmaxf(c, d)), e);
}
__device__ __forceinline__ float4 mask4(float4 t, unsigned bits) {
    t.x = (bits & 1u) ? 0.f : t.x;
    t.y = (bits & 2u) ? 0.f : t.y;
    t.z = (bits & 4u) ? 0.f : t.z;
    t.w = (bits & 8u) ? 0.f : t.w;
    return t;
}

__global__ __launch_bounds__(256) void nms_kernel(const float* __restrict__ s) {
    __shared__ __align__(16) float sT[TR*WP];
    __shared__ __align__(16) float TF[TR*WP];
    __shared__ ull Mb[TR];
    __shared__ ull SMKb[TR];

    int b = blockIdx.z, tid = threadIdx.x;
    int gx0 = blockIdx.x*32 - 10, gy0 = blockIdx.y*120 - 10;
    const float* sp = s + (size_t)b*HW;

    for (int i = tid; i < TR; i += 256) Mb[i] = 0ull;

    bool interior = (gx0 >= 2) && (gx0 + 54 <= W) && (gy0 >= 0) && (gy0 + TR <= H);
    if (interior) {
        for (int i = tid; i < TR*14; i += 256) {
            int r = i / 14, c4 = (i - (i/14)*14) * 4;
            *(float4*)&sT[r*WP + c4] =
                *(const float4*)&sp[(gy0 + r)*W + gx0 + c4 - 2];
        }
    } else {
        for (int i = tid; i < TR*WP; i += 256) {
            int r = i / WP, sc = i - r*WP;
            int gy = gy0 + r, gx = gx0 + sc - 2;
            sT[i] = (gy >= 0 && gy < H && gx >= 0 && gx < W) ? sp[gy*W + gx] : 0.f;
        }
    }
    __syncthreads();

#define F4(A, r, cb)  (*(const float4*)&A[(r)*WP + (cb)])
#define F4W(A, r, cb) (*(float4*)&A[(r)*WP + (cb)])

#define HWIN(r, cb, o0, o1, o2, o3)                                           \
    float4 L = F4(TF,r,(cb)-4), Md = F4(TF,r,cb), R = F4(TF,r,(cb)+4);        \
    float o0 = fmax5(L.z, L.w, Md.x, Md.y, Md.z);                             \
    float o1 = fmax5(L.w, Md.x, Md.y, Md.z, Md.w);                            \
    float o2 = fmax5(Md.x, Md.y, Md.z, Md.w, R.x);                            \
    float o3 = fmax5(Md.y, Md.z, Md.w, R.x, R.y);

    // ---- phase 1: vpass of raw scores, rows [2,138), all 14 chunks ----
    for (int i = tid; i < 136*14; i += 256) {
        int q = i/14; int r = 2+q; int cb = 4*(i - q*14);
        float4 v = f4max(f4max(F4(sT,r-2,cb), F4(sT,r-1,cb)),
                         f4max(F4(sT,r+1,cb), F4(sT,r+2,cb)));
        F4W(TF,r,cb) = f4max(v, F4(sT,r,cb));
    }
    __syncthreads();
    // ---- phase 2: hpass -> Mb, rows [2,138), cb 4..48 ----
    for (int i = tid; i < 136*12; i += 256) {
        int q = i/12; int r = 2+q; int cb = 4 + 4*(i - q*12);
        HWIN(r, cb, o0, o1, o2, o3)
        float4 t = F4(sT,r,cb);
        unsigned m = (t.x==o0 ? 1u:0u) | (t.y==o1 ? 2u:0u)
                   | (t.z==o2 ? 4u:0u) | (t.w==o3 ? 8u:0u);
        if (m) atomicOr(&Mb[r], (ull)m << cb);
    }
    __syncthreads();

    // ---- phase 3: suppression mask rows [4,136) ----
    if (tid < 132) {
        int r = 4 + tid;
        ull v = Mb[r-2] | Mb[r-1] | Mb[r] | Mb[r+1] | Mb[r+2];
        SMKb[r] = v | (v<<1) | (v<<2) | (v>>1) | (v>>2);
    }
    __syncthreads();

    // ---- phase 4: vpass of SS (= masked sT), rows [6,134), cb 4..48 ----
    for (int i = tid; i < 128*12; i += 256) {
        int q = i/12; int r = 6+q; int cb = 4 + 4*(i - q*12);
        float4 acc = make_float4(-FLT_MAX,-FLT_MAX,-FLT_MAX,-FLT_MAX);
        #pragma unroll
        for (int dr = -2; dr <= 2; dr++) {
            int rr = r + dr;
            unsigned bits = (unsigned)((SMKb[rr] >> cb) & 0xFull);
            acc = f4max(acc, mask4(F4(sT,rr,cb), bits));
        }
        F4W(TF,r,cb) = acc;
    }
    __syncthreads();
    // ---- phase 5: hpass -> Mb |= new peaks, rows [6,134), cb 8..44 ----
    for (int i = tid; i < 128*10; i += 256) {
        int q = i/10; int r = 6+q; int cb = 8 + 4*(i - q*10);
        HWIN(r, cb, o0, o1, o2, o3)
        unsigned smk = (unsigned)((SMKb[r] >> cb) & 0xFull);
        float4 ssv = mask4(F4(sT,r,cb), smk);
        unsigned add = ((ssv.x==o0 && !(smk&1u)) ? 1u:0u)
                     | ((ssv.y==o1 && !(smk&2u)) ? 2u:0u)
                     | ((ssv.z==o2 && !(smk&4u)) ? 4u:0u)
                     | ((ssv.w==o3 && !(smk&8u)) ? 8u:0u);
        if (add) atomicOr(&Mb[r], (ull)add << cb);
    }
    __syncthreads();

    // ---- phase 6: suppression mask rows [8,132) ----
    if (tid < 124) {
        int r = 8 + tid;
        ull v = Mb[r-2] | Mb[r-1] | Mb[r] | Mb[r+1] | Mb[r+2];
        SMKb[r] = v | (v<<1) | (v<<2) | (v>>1) | (v>>2);
    }
    __syncthreads();

    // ---- phase 7: vpass of SS4, rows [10,130), cb 8..44 ----
    for (int i = tid; i < 120*10; i += 256) {
        int q = i/10; int r = 10+q; int cb = 8 + 4*(i - q*10);
        float4 acc = make_float4(-FLT_MAX,-FLT_MAX,-FLT_MAX,-FLT_MAX);
        #pragma unroll
        for (int dr = -2; dr <= 2; dr++) {
            int rr = r + dr;
            unsigned bits = (unsigned)((SMKb[rr] >> cb) & 0xFull);
            acc = f4max(acc, mask4(F4(sT,rr,cb), bits));
        }
        F4W(TF,r,cb) = acc;
    }
    __syncthreads();
    // ---- phase 8: final + border + compaction, rows [10,130), cb 12..40 ----
    for (int i = tid; i < 120*8; i += 256) {
        int q = i/8; int r = 10+q; int cb = 12 + 4*(i - q*8);
        HWIN(r, cb, o0, o1, o2, o3)
        unsigned smk = (unsigned)((SMKb[r] >> cb) & 0xFull);
        unsigned mm  = (unsigned)((Mb[r]   >> cb) & 0xFull);
        float4 ssv = mask4(F4(sT,r,cb), smk);
        unsigned fin = mm
                     | ((ssv.x==o0 && !(smk&1u)) ? 1u:0u)
                     | ((ssv.y==o1 && !(smk&2u)) ? 2u:0u)
                     | ((ssv.z==o2 && !(smk&4u)) ? 4u:0u)
                     | ((ssv.w==o3 && !(smk&8u)) ? 8u:0u);
        while (fin) {
            int j = __ffs(fin) - 1;
            fin &= fin - 1;
            int gy = gy0 + r, gx = gx0 + cb + j - 2;
            if (gy >= 3 && gy < H-2 && gx >= 3 && gx < W-2) {
                int pos = atomicAdd(&g_cnt[b], 1);
                if (pos < CAP) {
                    g_cval[b*CAP + pos] = sT[r*WP + cb + j];
                    g_cidx[b*CAP + pos] = gy*W + gx;
                }
            }
        }
    }
}

// ============================================================================
// per-batch top-500: 3-level radix threshold + rank placement; re-zeroes g_cnt
// ============================================================================
__global__ __launch_bounds__(1024) void select_kernel() {
    __shared__ unsigned hist[2048];
    __shared__ unsigned gsum[64];
    __shared__ unsigned sel_key[1024];
    __shared__ int      sel_idx[1024];
    __shared__ int s_bsel, s_need, s_cnt;

    int b = blockIdx.x, tid = threadIdx.x;
    int lane = tid & 31, wid = tid >> 5;
    int n = min(g_cnt[b], CAP);
    __syncthreads();                     // all reads of g_cnt[b] complete ...
    if (tid == 0) g_cnt[b] = 0;          // ... before the reset (replay-safe)
    const float* vals = g_cval + b*CAP;
    const int*   idxs = g_cidx + b*CAP;

    unsigned prefix = 0;
    int need = TOPK;
    for (int level = 0; level < 3; level++) {
        int nbins = (level == 2) ? 1024 : 2048;
        for (int i = tid; i < nbins; i += 1024) hist[i] = 0;
        __syncthreads();
        for (int i = tid; i < n; i += 1024) {
            unsigned key = __float_as_uint(vals[i]);
            unsigned bin; bool ok;
            if (level == 0)      { ok = true;                  bin = key >> 21; }
            else if (level == 1) { ok = (key >> 21) == prefix; bin = (key >> 10) & 0x7FF; }
            else                 { ok = (key >> 10) == prefix; bin = key & 0x3FF; }
            if (ok) atomicAdd(&hist[bin], 1);
        }
        __syncthreads();
        {
            unsigned v = hist[tid];
            #pragma unroll
            for (int o = 16; o > 0; o >>= 1) v += __shfl_down_sync(~0u, v, o);
            if (lane == 0) gsum[wid] = v;
            if (nbins == 2048) {
                unsigned v2 = hist[tid + 1024];
                #pragma unroll
                for (int o = 16; o > 0; o >>= 1) v2 += __shfl_down_sync(~0u, v2, o);
                if (lane == 0) gsum[32 + wid] = v2;
            }
        }
        __syncthreads();
        if (wid == 0) {
            int ng = nbins >> 5;
            unsigned g0 = gsum[lane];
            unsigned g1 = (ng == 64) ? gsum[32 + lane] : 0u;
            unsigned s1 = g1;
            #pragma unroll
            for (int o = 1; o < 32; o <<= 1) { unsigned t = __shfl_down_sync(~0u, s1, o); if (lane + o < 32) s1 += t; }
            unsigned tot1 = __shfl_sync(~0u, s1, 0);
            unsigned s0 = g0;
            #pragma unroll
            for (int o = 1; o < 32; o <<= 1) { unsigned t = __shfl_down_sync(~0u, s0, o); if (lane + o < 32) s0 += t; }
            s0 += tot1;
            unsigned b0 = __ballot_sync(~0u, s0 >= (unsigned)need);
            unsigned b1 = __ballot_sync(~0u, (ng == 64) && (s1 >= (unsigned)need));
            int gstar; unsigned suf_after;
            if (b1) {
                int j = 31 - __clz(b1);
                gstar = 32 + j;
                suf_after = (j == 31) ? 0u : __shfl_sync(~0u, s1, j + 1);
            } else {
                gstar = 31 - __clz(b0);
                suf_after = (gstar == 31) ? tot1 : __shfl_sync(~0u, s0, gstar + 1);
            }
            int need_g = need - (int)suf_after;
            unsigned hs = hist[gstar*32 + lane];
            #pragma unroll
            for (int o = 1; o < 32; o <<= 1) { unsigned t = __shfl_down_sync(~0u, hs, o); if (lane + o < 32) hs += t; }
            unsigned bb = __ballot_sync(~0u, hs >= (unsigned)need_g);
            int bstar = 31 - __clz(bb);
            unsigned bsuf = (bstar == 31) ? 0u : __shfl_sync(~0u, hs, bstar + 1);
            if (lane == 0) { s_bsel = gstar*32 + bstar; s_need = need_g - (int)bsuf; }
        }
        __syncthreads();
        if (level == 0)      prefix = (unsigned)s_bsel;
        else if (level == 1) prefix = (prefix << 11) | (unsigned)s_bsel;
        else                 prefix = (prefix << 10) | (unsigned)s_bsel;
        need = s_need;
        __syncthreads();
    }
    unsigned T = prefix;

    if (tid == 0) s_cnt = 0;
    __syncthreads();
    for (int i = tid; i < n; i += 1024) {
        unsigned key = __float_as_uint(vals[i]);
        if (key >= T) {
            int p = atomicAdd(&s_cnt, 1);
            if (p < 1024) { sel_key[p] = key; sel_idx[p] = idxs[i]; }
        }
    }
    __syncthreads();
    int cnt = min(s_cnt, 1024);
    if (tid < cnt) {
        unsigned ki = sel_key[tid];
        int ii = sel_idx[tid];
        int rank = 0;
        for (int j = 0; j < cnt; j++) {
            unsigned kj = sel_key[j];
            int ij = sel_idx[j];
            rank += (kj > ki) || (kj == ki && ij < ii);
        }
        if (rank < TOPK) g_topk[b*TOPK + rank] = ii;
    }
}

__device__ __forceinline__ float wmax(float v) {
    #pragma unroll
    for (int o = 16; o > 0; o >>= 1) v = fmaxf(v, __shfl_xor_sync(0xffffffffu, v, o));
    return v;
}

// ============================================================================
// fused patch refinement + descriptor sampling: 8 keypoints per 512-thr block
// ============================================================================
__global__ __launch_bounds__(512) void patch_desc_kernel(
        const float* __restrict__ s, const float* __restrict__ dmap,
        float* __restrict__ out) {
    __shared__ float spx[8], spy[8];
    __shared__ float part[16];
    int tid = threadIdx.x;
    int kbase = blockIdx.x * 8;
    int wid = tid >> 5, lane = tid & 31;

    // ---- phase 1: warps 0..7 each refine one keypoint ----
    if (wid < 8) {
        int gw = kbase + wid;
        int b = gw / TOPK;
        int p = g_topk[gw];
        int y = p / W, x = p - y*W;
        int ky = lane / 5, kx = lane - ky*5;
        float v = -FLT_MAX;
        if (lane < 25) v = s[(size_t)b*HW + (y + ky - 2)*W + (x + kx - 2)];
        float mx = wmax(v);
        float gxk = (float)(kx - 2), gyk = (float)(ky - 2);
        float e = (lane < 25) ? __expf((v - mx) * 10.f) : 0.f;
        float s0 = e, s1 = e*gxk, s2 = e*gyk, s3 = e*(gxk*gxk + gyk*gyk);
        #pragma unroll
        for (int o = 16; o > 0; o >>= 1) {
            s0 += __shfl_xor_sync(~0u, s0, o);
            s1 += __shfl_xor_sync(~0u, s1, o);
            s2 += __shfl_xor_sync(~0u, s2, o);
            s3 += __shfl_xor_sync(~0u, s3, o);
        }
        if (lane == 0) {
            float denom = s0 + 1e-12f;
            float inv = 1.f / denom;
            float xr = s1 * inv, yr = s2 * inv;
            float disp = (s3 - 2.f*xr*s1 - 2.f*yr*s2 + (xr*xr + yr*yr)*s0) * 0.25f * inv;
            float fx = (float)x + xr, fy = (float)y + yr;
            float gx = fx / (float)(W-1) * 2.f - 1.f;
            float gy = fy / (float)(H-1) * 2.f - 1.f;
            out[KXY_OFF + gw*2 + 0] = gx;
            out[KXY_OFF + gw*2 + 1] = gy;
            out[DISP_OFF + gw] = disp;

            float px = fminf(fmaxf((gx + 1.f) * 0.5f * (float)(W-1), 0.f), (float)(W-1));
            float py = fminf(fmaxf((gy + 1.f) * 0.5f * (float)(H-1), 0.f), (float)(H-1));
            spx[wid] = px; spy[wid] = py;
            int x0 = (int)floorf(px), y0 = (int)floorf(py);
            float wx = px - (float)x0, wy = py - (float)y0;
            int x1 = min(x0 + 1, W-1), y1 = min(y0 + 1, H-1);
            const float* sb = s + (size_t)b*HW;
            float v00 = sb[y0*W + x0], v01 = sb[y0*W + x1];
            float v10 = sb[y1*W + x0], v11 = sb[y1*W + x1];
            out[KPS_OFF + gw] = v00*(1.f-wx)*(1.f-wy) + v01*wx*(1.f-wy)
                              + v10*(1.f-wx)*wy       + v11*wx*wy;
        }
    }
    __syncthreads();

    // ---- phase 2: descriptor gather + L2 norm (64 threads / keypoint) ----
    int kl = tid >> 6;            // 0..7
    int c  = tid & 63;
    int g  = kbase + kl;
    int b  = g / TOPK;
    float px = spx[kl], py = spy[kl];
    int x0 = (int)floorf(px), y0 = (int)floorf(py);
    float wx = px - (float)x0, wy = py - (float)y0;
    int x1 = min(x0 + 1, W-1), y1 = min(y0 + 1, H-1);
    const float* base = dmap + ((size_t)b*64 + c) * (size_t)HW;
    float v00 = base[y0*W + x0], v01 = base[y0*W + x1];
    float v10 = base[y1*W + x0], v11 = base[y1*W + x1];
    float d = v00*(1.f-wx)*(1.f-wy) + v01*wx*(1.f-wy)
            + v10*(1.f-wx)*wy       + v11*wx*wy;

    float ss = d * d;
    #pragma unroll
    for (int o = 16; o > 0; o >>= 1) ss += __shfl_xor_sync(0xffffffffu, ss, o);
    if (lane == 0) part[wid] = ss;
    __syncthreads();
    float tot = part[2*kl] + part[2*kl + 1];
    float nrm = fmaxf(sqrtf(tot), 1e-12f);
    out[DESC_OFF + g*64 + c] = d / nrm;
}

extern "C" void kernel_launch(void* const* d_in, const int* in_sizes, int n_in,
                              void* d_out, int out_size) {
    const float* scores = (const float*)d_in[0];
    const float* descs  = (const float*)d_in[1];
    float* out = (float*)d_out;

    nms_kernel<<<dim3(W/32, H/120, B), 256>>>(scores);
    select_kernel<<<B, 1024>>>();
    patch_desc_kernel<<<NKP/8, 512>>>(scores, descs, out);
}

// round 14
// speedup vs baseline: 1.1256x; 1.1256x over previous
#include <cuda_runtime.h>
#include <math.h>
#include <float.h>

#define B 8
#define H 480
#define W 640
#define HW (H*W)
#define TOPK 500
#define NKP (B*TOPK)
#define CAP 131072

#define KXY_OFF 0
#define DESC_OFF (NKP*2)
#define KPS_OFF (DESC_OFF + NKP*64)
#define DISP_OFF (KPS_OFF + NKP)

typedef unsigned long long ull;

// ---------------- device scratch ----------------
__device__ float g_cval[B*CAP];
__device__ int   g_cidx[B*CAP];
__device__ int   g_cnt[B];          // zero at load; re-zeroed by select (replay-safe)
__device__ int   g_topk[NKP];

// ============================================================================
// Fused NMS: 32-wide x 60-tall output tile, radius-10 halo -> 80 rows x 56
// padded cols (sc in [2,54)). smem 37.1 KB -> 6 CTAs/SM. Same proven phase
// structure as the 37.7us kernel; masks bit-packed one ull per row; phases
// 5/8 early-out on fully-suppressed chunks.
// ============================================================================
#define WP 56
#define TRR 80   /* tile rows */

__device__ __forceinline__ float4 f4max(float4 a, float4 b) {
    return make_float4(fmaxf(a.x,b.x), fmaxf(a.y,b.y), fmaxf(a.z,b.z), fmaxf(a.w,b.w));
}
__device__ __forceinline__ float fmax5(float a, float b, float c, float d, float e) {
    return fmaxf(fmaxf(fmaxf(a, b), fmaxf(c, d)), e);
}
__device__ __forceinline__ float4 mask4(float4 t, unsigned bits) {
    t.x = (bits & 1u) ? 0.f : t.x;
    t.y = (bits & 2u) ? 0.f : t.y;
    t.z = (bits & 4u) ? 0.f : t.z;
    t.w = (bits & 8u) ? 0.f : t.w;
    return t;
}

__global__ __launch_bounds__(256) void nms_kernel(const float* __restrict__ s) {
    __shared__ __align__(16) float sT[TRR*WP];
    __shared__ __align__(16) float TF[TRR*WP];
    __shared__ ull Mb[TRR];
    __shared__ ull SMKb[TRR];

    int b = blockIdx.z, tid = threadIdx.x;
    int gx0 = blockIdx.x*32 - 10, gy0 = blockIdx.y*60 - 10;
    const float* sp = s + (size_t)b*HW;

    if (tid < TRR) Mb[tid] = 0ull;

    bool interior = (gx0 >= 2) && (gx0 + 54 <= W) && (gy0 >= 0) && (gy0 + TRR <= H);
    if (interior) {
        for (int i = tid; i < TRR*14; i += 256) {
            int r = i / 14, c4 = (i - (i/14)*14) * 4;
            *(float4*)&sT[r*WP + c4] =
                *(const float4*)&sp[(gy0 + r)*W + gx0 + c4 - 2];
        }
    } else {
        for (int i = tid; i < TRR*WP; i += 256) {
            int r = i / WP, sc = i - r*WP;
            int gy = gy0 + r, gx = gx0 + sc - 2;
            sT[i] = (gy >= 0 && gy < H && gx >= 0 && gx < W) ? sp[gy*W + gx] : 0.f;
        }
    }
    __syncthreads();

#define F4(A, r, cb)  (*(const float4*)&A[(r)*WP + (cb)])
#define F4W(A, r, cb) (*(float4*)&A[(r)*WP + (cb)])

#define HWIN(r, cb, o0, o1, o2, o3)                                           \
    float4 L = F4(TF,r,(cb)-4), Md = F4(TF,r,cb), R = F4(TF,r,(cb)+4);        \
    float o0 = fmax5(L.z, L.w, Md.x, Md.y, Md.z);                             \
    float o1 = fmax5(L.w, Md.x, Md.y, Md.z, Md.w);                            \
    float o2 = fmax5(Md.x, Md.y, Md.z, Md.w, R.x);                            \
    float o3 = fmax5(Md.y, Md.z, Md.w, R.x, R.y);

    // ---- phase 1: vpass of raw scores, rows [2,78), all 14 chunks ----
    for (int i = tid; i < 76*14; i += 256) {
        int q = i/14; int r = 2+q; int cb = 4*(i - q*14);
        float4 v = f4max(f4max(F4(sT,r-2,cb), F4(sT,r-1,cb)),
                         f4max(F4(sT,r+1,cb), F4(sT,r+2,cb)));
        F4W(TF,r,cb) = f4max(v, F4(sT,r,cb));
    }
    __syncthreads();
    // ---- phase 2: hpass -> Mb, rows [2,78), cb 4..48 ----
    for (int i = tid; i < 76*12; i += 256) {
        int q = i/12; int r = 2+q; int cb = 4 + 4*(i - q*12);
        HWIN(r, cb, o0, o1, o2, o3)
        float4 t = F4(sT,r,cb);
        unsigned m = (t.x==o0 ? 1u:0u) | (t.y==o1 ? 2u:0u)
                   | (t.z==o2 ? 4u:0u) | (t.w==o3 ? 8u:0u);
        if (m) atomicOr(&Mb[r], (ull)m << cb);
    }
    __syncthreads();

    // ---- phase 3: suppression mask rows [4,76) ----
    if (tid < 72) {
        int r = 4 + tid;
        ull v = Mb[r-2] | Mb[r-1] | Mb[r] | Mb[r+1] | Mb[r+2];
        SMKb[r] = v | (v<<1) | (v<<2) | (v>>1) | (v>>2);
    }
    __syncthreads();

    // ---- phase 4: vpass of SS (= masked sT), rows [6,74), cb 4..48 ----
    for (int i = tid; i < 68*12; i += 256) {
        int q = i/12; int r = 6+q; int cb = 4 + 4*(i - q*12);
        float4 acc = make_float4(-FLT_MAX,-FLT_MAX,-FLT_MAX,-FLT_MAX);
        #pragma unroll
        for (int dr = -2; dr <= 2; dr++) {
            int rr = r + dr;
            unsigned bits = (unsigned)((SMKb[rr] >> cb) & 0xFull);
            acc = f4max(acc, mask4(F4(sT,rr,cb), bits));
        }
        F4W(TF,r,cb) = acc;
    }
    __syncthreads();
    // ---- phase 5: hpass -> Mb |= new peaks, rows [6,74), cb 8..44 ----
    for (int i = tid; i < 68*10; i += 256) {
        int q = i/10; int r = 6+q; int cb = 8 + 4*(i - q*10);
        unsigned smk = (unsigned)((SMKb[r] >> cb) & 0xFull);
        if (smk == 0xFu) continue;       // all 4 centers suppressed: no new peak
        HWIN(r, cb, o0, o1, o2, o3)
        float4 ssv = mask4(F4(sT,r,cb), smk);
        unsigned add = ((ssv.x==o0 && !(smk&1u)) ? 1u:0u)
                     | ((ssv.y==o1 && !(smk&2u)) ? 2u:0u)
                     | ((ssv.z==o2 && !(smk&4u)) ? 4u:0u)
                     | ((ssv.w==o3 && !(smk&8u)) ? 8u:0u);
        if (add) atomicOr(&Mb[r], (ull)add << cb);
    }
    __syncthreads();

    // ---- phase 6: suppression mask rows [8,72) ----
    if (tid < 64) {
        int r = 8 + tid;
        ull v = Mb[r-2] | Mb[r-1] | Mb[r] | Mb[r+1] | Mb[r+2];
        SMKb[r] = v | (v<<1) | (v<<2) | (v>>1) | (v>>2);
    }
    __syncthreads();

    // ---- phase 7: vpass of SS4, rows [10,70), cb 8..44 ----
    for (int i = tid; i < 60*10; i += 256) {
        int q = i/10; int r = 10+q; int cb = 8 + 4*(i - q*10);
        float4 acc = make_float4(-FLT_MAX,-FLT_MAX,-FLT_MAX,-FLT_MAX);
        #pragma unroll
        for (int dr = -2; dr <= 2; dr++) {
            int rr = r + dr;
            unsigned bits = (unsigned)((SMKb[rr] >> cb) & 0xFull);
            acc = f4max(acc, mask4(F4(sT,rr,cb), bits));
        }
        F4W(TF,r,cb) = acc;
    }
    __syncthreads();
    // ---- phase 8: final + border + compaction, rows [10,70), cb 12..40 ----
    for (int i = tid; i < 60*8; i += 256) {
        int q = i/8; int r = 10+q; int cb = 12 + 4*(i - q*8);
        unsigned smk = (unsigned)((SMKb[r] >> cb) & 0xFull);
        unsigned mm  = (unsigned)((Mb[r]   >> cb) & 0xFull);
        unsigned fin;
        if (smk == 0xFu) {
            fin = mm;                    // no new peak possible; keep existing
        } else {
            HWIN(r, cb, o0, o1, o2, o3)
            float4 ssv = mask4(F4(sT,r,cb), smk);
            fin = mm
                | ((ssv.x==o0 && !(smk&1u)) ? 1u:0u)
                | ((ssv.y==o1 && !(smk&2u)) ? 2u:0u)
                | ((ssv.z==o2 && !(smk&4u)) ? 4u:0u)
                | ((ssv.w==o3 && !(smk&8u)) ? 8u:0u);
        }
        while (fin) {
            int j = __ffs(fin) - 1;
            fin &= fin - 1;
            int gy = gy0 + r, gx = gx0 + cb + j - 2;
            if (gy >= 3 && gy < H-2 && gx >= 3 && gx < W-2) {
                int pos = atomicAdd(&g_cnt[b], 1);
                if (pos < CAP) {
                    g_cval[b*CAP + pos] = sT[r*WP + cb + j];
                    g_cidx[b*CAP + pos] = gy*W + gx;
                }
            }
        }
    }
}

// ============================================================================
// per-batch top-500: 3-level radix threshold + rank placement; re-zeroes g_cnt
// ============================================================================
__global__ __launch_bounds__(1024) void select_kernel() {
    __shared__ unsigned hist[2048];
    __shared__ unsigned gsum[64];
    __shared__ unsigned sel_key[1024];
    __shared__ int      sel_idx[1024];
    __shared__ int s_bsel, s_need, s_cnt;

    int b = blockIdx.x, tid = threadIdx.x;
    int lane = tid & 31, wid = tid >> 5;
    int n = min(g_cnt[b], CAP);
    __syncthreads();                     // all reads of g_cnt[b] complete ...
    if (tid == 0) g_cnt[b] = 0;          // ... before the reset (replay-safe)
    const float* vals = g_cval + b*CAP;
    const int*   idxs = g_cidx + b*CAP;

    unsigned prefix = 0;
    int need = TOPK;
    for (int level = 0; level < 3; level++) {
        int nbins = (level == 2) ? 1024 : 2048;
        for (int i = tid; i < nbins; i += 1024) hist[i] = 0;
        __syncthreads();
        for (int i = tid; i < n; i += 1024) {
            unsigned key = __float_as_uint(vals[i]);
            unsigned bin; bool ok;
            if (level == 0)      { ok = true;                  bin = key >> 21; }
            else if (level == 1) { ok = (key >> 21) == prefix; bin = (key >> 10) & 0x7FF; }
            else                 { ok = (key >> 10) == prefix; bin = key & 0x3FF; }
            if (ok) atomicAdd(&hist[bin], 1);
        }
        __syncthreads();
        {
            unsigned v = hist[tid];
            #pragma unroll
            for (int o = 16; o > 0; o >>= 1) v += __shfl_down_sync(~0u, v, o);
            if (lane == 0) gsum[wid] = v;
            if (nbins == 2048) {
                unsigned v2 = hist[tid + 1024];
                #pragma unroll
                for (int o = 16; o > 0; o >>= 1) v2 += __shfl_down_sync(~0u, v2, o);
                if (lane == 0) gsum[32 + wid] = v2;
            }
        }
        __syncthreads();
        if (wid == 0) {
            int ng = nbins >> 5;
            unsigned g0 = gsum[lane];
            unsigned g1 = (ng == 64) ? gsum[32 + lane] : 0u;
            unsigned s1 = g1;
            #pragma unroll
            for (int o = 1; o < 32; o <<= 1) { unsigned t = __shfl_down_sync(~0u, s1, o); if (lane + o < 32) s1 += t; }
            unsigned tot1 = __shfl_sync(~0u, s1, 0);
            unsigned s0 = g0;
            #pragma unroll
            for (int o = 1; o < 32; o <<= 1) { unsigned t = __shfl_down_sync(~0u, s0, o); if (lane + o < 32) s0 += t; }
            s0 += tot1;
            unsigned b0 = __ballot_sync(~0u, s0 >= (unsigned)need);
            unsigned b1 = __ballot_sync(~0u, (ng == 64) && (s1 >= (unsigned)need));
            int gstar; unsigned suf_after;
            if (b1) {
                int j = 31 - __clz(b1);
                gstar = 32 + j;
                suf_after = (j == 31) ? 0u : __shfl_sync(~0u, s1, j + 1);
            } else {
                gstar = 31 - __clz(b0);
                suf_after = (gstar == 31) ? tot1 : __shfl_sync(~0u, s0, gstar + 1);
            }
            int need_g = need - (int)suf_after;
            unsigned hs = hist[gstar*32 + lane];
            #pragma unroll
            for (int o = 1; o < 32; o <<= 1) { unsigned t = __shfl_down_sync(~0u, hs, o); if (lane + o < 32) hs += t; }
            unsigned bb = __ballot_sync(~0u, hs >= (unsigned)need_g);
            int bstar = 31 - __clz(bb);
            unsigned bsuf = (bstar == 31) ? 0u : __shfl_sync(~0u, hs, bstar + 1);
            if (lane == 0) { s_bsel = gstar*32 + bstar; s_need = need_g - (int)bsuf; }
        }
        __syncthreads();
        if (level == 0)      prefix = (unsigned)s_bsel;
        else if (level == 1) prefix = (prefix << 11) | (unsigned)s_bsel;
        else                 prefix = (prefix << 10) | (unsigned)s_bsel;
        need = s_need;
        __syncthreads();
    }
    unsigned T = prefix;

    if (tid == 0) s_cnt = 0;
    __syncthreads();
    for (int i = tid; i < n; i += 1024) {
        unsigned key = __float_as_uint(vals[i]);
        if (key >= T) {
            int p = atomicAdd(&s_cnt, 1);
            if (p < 1024) { sel_key[p] = key; sel_idx[p] = idxs[i]; }
        }
    }
    __syncthreads();
    int cnt = min(s_cnt, 1024);
    if (tid < cnt) {
        unsigned ki = sel_key[tid];
        int ii = sel_idx[tid];
        int rank = 0;
        for (int j = 0; j < cnt; j++) {
            unsigned kj = sel_key[j];
            int ij = sel_idx[j];
            rank += (kj > ki) || (kj == ki && ij < ii);
        }
        if (rank < TOPK) g_topk[b*TOPK + rank] = ii;
    }
}

__device__ __forceinline__ float wmax(float v) {
    #pragma unroll
    for (int o = 16; o > 0; o >>= 1) v = fmaxf(v, __shfl_xor_sync(0xffffffffu, v, o));
    return v;
}

// ============================================================================
// fused patch refinement + descriptor sampling: 8 keypoints per 512-thr block
// ============================================================================
__global__ __launch_bounds__(512) void patch_desc_kernel(
        const float* __restrict__ s, const float* __restrict__ dmap,
        float* __restrict__ out) {
    __shared__ float spx[8], spy[8];
    __shared__ float part[16];
    int tid = threadIdx.x;
    int kbase = blockIdx.x * 8;
    int wid = tid >> 5, lane = tid & 31;

    // ---- phase 1: warps 0..7 each refine one keypoint ----
    if (wid < 8) {
        int gw = kbase + wid;
        int b = gw / TOPK;
        int p = g_topk[gw];
        int y = p / W, x = p - y*W;
        int ky = lane / 5, kx = lane - ky*5;
        float v = -FLT_MAX;
        if (lane < 25) v = s[(size_t)b*HW + (y + ky - 2)*W + (x + kx - 2)];
        float mx = wmax(v);
        float gxk = (float)(kx - 2), gyk = (float)(ky - 2);
        float e = (lane < 25) ? __expf((v - mx) * 10.f) : 0.f;
        float s0 = e, s1 = e*gxk, s2 = e*gyk, s3 = e*(gxk*gxk + gyk*gyk);
        #pragma unroll
        for (int o = 16; o > 0; o >>= 1) {
            s0 += __shfl_xor_sync(~0u, s0, o);
            s1 += __shfl_xor_sync(~0u, s1, o);
            s2 += __shfl_xor_sync(~0u, s2, o);
            s3 += __shfl_xor_sync(~0u, s3, o);
        }
        if (lane == 0) {
            float denom = s0 + 1e-12f;
            float inv = 1.f / denom;
            float xr = s1 * inv, yr = s2 * inv;
            float disp = (s3 - 2.f*xr*s1 - 2.f*yr*s2 + (xr*xr + yr*yr)*s0) * 0.25f * inv;
            float fx = (float)x + xr, fy = (float)y + yr;
            float gx = fx / (float)(W-1) * 2.f - 1.f;
            float gy = fy / (float)(H-1) * 2.f - 1.f;
            out[KXY_OFF + gw*2 + 0] = gx;
            out[KXY_OFF + gw*2 + 1] = gy;
            out[DISP_OFF + gw] = disp;

            float px = fminf(fmaxf((gx + 1.f) * 0.5f * (float)(W-1), 0.f), (float)(W-1));
            float py = fminf(fmaxf((gy + 1.f) * 0.5f * (float)(H-1), 0.f), (float)(H-1));
            spx[wid] = px; spy[wid] = py;
            int x0 = (int)floorf(px), y0 = (int)floorf(py);
            float wx = px - (float)x0, wy = py - (float)y0;
            int x1 = min(x0 + 1, W-1), y1 = min(y0 + 1, H-1);
            const float* sb = s + (size_t)b*HW;
            float v00 = sb[y0*W + x0], v01 = sb[y0*W + x1];
            float v10 = sb[y1*W + x0], v11 = sb[y1*W + x1];
            out[KPS_OFF + gw] = v00*(1.f-wx)*(1.f-wy) + v01*wx*(1.f-wy)
                              + v10*(1.f-wx)*wy       + v11*wx*wy;
        }
    }
    __syncthreads();

    // ---- phase 2: descriptor gather + L2 norm (64 threads / keypoint) ----
    int kl = tid >> 6;            // 0..7
    int c  = tid & 63;
    int g  = kbase + kl;
    int b  = g / TOPK;
    float px = spx[kl], py = spy[kl];
    int x0 = (int)floorf(px), y0 = (int)floorf(py);
    float wx = px - (float)x0, wy = py - (float)y0;
    int x1 = min(x0 + 1, W-1), y1 = min(y0 + 1, H-1);
    const float* base = dmap + ((size_t)b*64 + c) * (size_t)HW;
    float v00 = base[y0*W + x0], v01 = base[y0*W + x1];
    float v10 = base[y1*W + x0], v11 = base[y1*W + x1];
    float d = v00*(1.f-wx)*(1.f-wy) + v01*wx*(1.f-wy)
            + v10*(1.f-wx)*wy       + v11*wx*wy;

    float ss = d * d;
    #pragma unroll
    for (int o = 16; o > 0; o >>= 1) ss += __shfl_xor_sync(0xffffffffu, ss, o);
    if (lane == 0) part[wid] = ss;
    __syncthreads();
    float tot = part[2*kl] + part[2*kl + 1];
    float nrm = fmaxf(sqrtf(tot), 1e-12f);
    out[DESC_OFF + g*64 + c] = d / nrm;
}

extern "C" void kernel_launch(void* const* d_in, const int* in_sizes, int n_in,
                              void* d_out, int out_size) {
    const float* scores = (const float*)d_in[0];
    const float* descs  = (const float*)d_in[1];
    float* out = (float*)d_out;

    nms_kernel<<<dim3(W/32, H/60, B), 256>>>(scores);
    select_kernel<<<B, 1024>>>();
    patch_desc_kernel<<<NKP/8, 512>>>(scores, descs, out);
}

// round 15
// speedup vs baseline: 1.1480x; 1.0199x over previous
#include <cuda_runtime.h>
#include <math.h>
#include <float.h>

#define B 8
#define H 480
#define W 640
#define HW (H*W)
#define TOPK 500
#define NKP (B*TOPK)
#define CAP 131072

#define KXY_OFF 0
#define DESC_OFF (NKP*2)
#define KPS_OFF (DESC_OFF + NKP*64)
#define DISP_OFF (KPS_OFF + NKP)

typedef unsigned long long ull;

// ---------------- device scratch ----------------
__device__ float g_cval[B*CAP];
__device__ int   g_cidx[B*CAP];
__device__ int   g_cnt[B];          // zero at load; re-zeroed by select (replay-safe)
__device__ int   g_topk[NKP];

// ============================================================================
// Fused NMS (R10-proven 37.7us): 32x32 output tile, radius-10 halo ->
// 52 rows x 56 padded cols. Masks bit-packed one ull per row.
// ============================================================================
#define WP 56

__device__ __forceinline__ float4 f4max(float4 a, float4 b) {
    return make_float4(fmaxf(a.x,b.x), fmaxf(a.y,b.y), fmaxf(a.z,b.z), fmaxf(a.w,b.w));
}
__device__ __forceinline__ float fmax5(float a, float b, float c, float d, float e) {
    return fmaxf(fmaxf(fmaxf(a, b), fmaxf(c, d)), e);
}
__device__ __forceinline__ float4 mask4(float4 t, unsigned bits) {
    t.x = (bits & 1u) ? 0.f : t.x;
    t.y = (bits & 2u) ? 0.f : t.y;
    t.z = (bits & 4u) ? 0.f : t.z;
    t.w = (bits & 8u) ? 0.f : t.w;
    return t;
}

__global__ __launch_bounds__(256) void nms_kernel(const float* __restrict__ s) {
    __shared__ __align__(16) float sT[52*WP];
    __shared__ __align__(16) float TF[52*WP];
    __shared__ ull Mb[52];
    __shared__ ull SMKb[52];

    int b = blockIdx.z, tid = threadIdx.x;
    int gx0 = blockIdx.x*32 - 10, gy0 = blockIdx.y*32 - 10;
    const float* sp = s + (size_t)b*HW;

    if (tid < 52) Mb[tid] = 0ull;

    bool interior = (gx0 >= 2) && (gx0 + 54 <= W) && (gy0 >= 0) && (gy0 + 52 <= H);
    if (interior) {
        for (int i = tid; i < 52*14; i += 256) {
            int r = i / 14, c4 = (i - (i/14)*14) * 4;
            *(float4*)&sT[r*WP + c4] =
                *(const float4*)&sp[(gy0 + r)*W + gx0 + c4 - 2];
        }
    } else {
        for (int i = tid; i < 52*WP; i += 256) {
            int r = i / WP, sc = i - r*WP;
            int gy = gy0 + r, gx = gx0 + sc - 2;
            sT[i] = (gy >= 0 && gy < H && gx >= 0 && gx < W) ? sp[gy*W + gx] : 0.f;
        }
    }
    __syncthreads();

#define F4(A, r, cb)  (*(const float4*)&A[(r)*WP + (cb)])
#define F4W(A, r, cb) (*(float4*)&A[(r)*WP + (cb)])

#define HWIN(r, cb, o0, o1, o2, o3)                                           \
    float4 L = F4(TF,r,(cb)-4), Md = F4(TF,r,cb), R = F4(TF,r,(cb)+4);        \
    float o0 = fmax5(L.z, L.w, Md.x, Md.y, Md.z);                             \
    float o1 = fmax5(L.w, Md.x, Md.y, Md.z, Md.w);                            \
    float o2 = fmax5(Md.x, Md.y, Md.z, Md.w, R.x);                            \
    float o3 = fmax5(Md.y, Md.z, Md.w, R.x, R.y);

    // ---- phase 1: vpass of raw scores, rows [2,50), all 14 chunks ----
    for (int i = tid; i < 48*14; i += 256) {
        int q = i/14; int r = 2+q; int cb = 4*(i - q*14);
        float4 v = f4max(f4max(F4(sT,r-2,cb), F4(sT,r-1,cb)),
                         f4max(F4(sT,r+1,cb), F4(sT,r+2,cb)));
        F4W(TF,r,cb) = f4max(v, F4(sT,r,cb));
    }
    __syncthreads();
    // ---- phase 2: hpass -> Mb, rows [2,50), cb 4..48 ----
    for (int i = tid; i < 48*12; i += 256) {
        int q = i/12; int r = 2+q; int cb = 4 + 4*(i - q*12);
        HWIN(r, cb, o0, o1, o2, o3)
        float4 t = F4(sT,r,cb);
        unsigned m = (t.x==o0 ? 1u:0u) | (t.y==o1 ? 2u:0u)
                   | (t.z==o2 ? 4u:0u) | (t.w==o3 ? 8u:0u);
        if (m) atomicOr(&Mb[r], (ull)m << cb);
    }
    __syncthreads();

    // ---- phase 3: suppression mask rows [4,48) ----
    if (tid < 44) {
        int r = 4 + tid;
        ull v = Mb[r-2] | Mb[r-1] | Mb[r] | Mb[r+1] | Mb[r+2];
        SMKb[r] = v | (v<<1) | (v<<2) | (v>>1) | (v>>2);
    }
    __syncthreads();

    // ---- phase 4: vpass of SS (= masked sT), rows [6,46), cb 4..48 ----
    for (int i = tid; i < 40*12; i += 256) {
        int q = i/12; int r = 6+q; int cb = 4 + 4*(i - q*12);
        float4 acc = make_float4(-FLT_MAX,-FLT_MAX,-FLT_MAX,-FLT_MAX);
        #pragma unroll
        for (int dr = -2; dr <= 2; dr++) {
            int rr = r + dr;
            unsigned bits = (unsigned)((SMKb[rr] >> cb) & 0xFull);
            acc = f4max(acc, mask4(F4(sT,rr,cb), bits));
        }
        F4W(TF,r,cb) = acc;
    }
    __syncthreads();
    // ---- phase 5: hpass -> Mb |= new peaks, rows [6,46), cb 8..44 ----
    for (int i = tid; i < 40*10; i += 256) {
        int q = i/10; int r = 6+q; int cb = 8 + 4*(i - q*10);
        HWIN(r, cb, o0, o1, o2, o3)
        unsigned smk = (unsigned)((SMKb[r] >> cb) & 0xFull);
        float4 ssv = mask4(F4(sT,r,cb), smk);
        unsigned add = ((ssv.x==o0 && !(smk&1u)) ? 1u:0u)
                     | ((ssv.y==o1 && !(smk&2u)) ? 2u:0u)
                     | ((ssv.z==o2 && !(smk&4u)) ? 4u:0u)
                     | ((ssv.w==o3 && !(smk&8u)) ? 8u:0u);
        if (add) atomicOr(&Mb[r], (ull)add << cb);
    }
    __syncthreads();

    // ---- phase 6: suppression mask rows [8,44) ----
    if (tid < 36) {
        int r = 8 + tid;
        ull v = Mb[r-2] | Mb[r-1] | Mb[r] | Mb[r+1] | Mb[r+2];
        SMKb[r] = v | (v<<1) | (v<<2) | (v>>1) | (v>>2);
    }
    __syncthreads();

    // ---- phase 7: vpass of SS4, rows [10,42), cb 8..44 ----
    for (int i = tid; i < 32*10; i += 256) {
        int q = i/10; int r = 10+q; int cb = 8 + 4*(i - q*10);
        float4 acc = make_float4(-FLT_MAX,-FLT_MAX,-FLT_MAX,-FLT_MAX);
        #pragma unroll
        for (int dr = -2; dr <= 2; dr++) {
            int rr = r + dr;
            unsigned bits = (unsigned)((SMKb[rr] >> cb) & 0xFull);
            acc = f4max(acc, mask4(F4(sT,rr,cb), bits));
        }
        F4W(TF,r,cb) = acc;
    }
    __syncthreads();
    // ---- phase 8: final + border + compaction, rows [10,42), cb 12..40 ----
    for (int i = tid; i < 32*8; i += 256) {
        int q = i/8; int r = 10+q; int cb = 12 + 4*(i - q*8);
        HWIN(r, cb, o0, o1, o2, o3)
        unsigned smk = (unsigned)((SMKb[r] >> cb) & 0xFull);
        unsigned mm  = (unsigned)((Mb[r]   >> cb) & 0xFull);
        float4 ssv = mask4(F4(sT,r,cb), smk);
        unsigned fin = mm
                     | ((ssv.x==o0 && !(smk&1u)) ? 1u:0u)
                     | ((ssv.y==o1 && !(smk&2u)) ? 2u:0u)
                     | ((ssv.z==o2 && !(smk&4u)) ? 4u:0u)
                     | ((ssv.w==o3 && !(smk&8u)) ? 8u:0u);
        while (fin) {
            int j = __ffs(fin) - 1;
            fin &= fin - 1;
            int gy = gy0 + r, gx = gx0 + cb + j - 2;
            if (gy >= 3 && gy < H-2 && gx >= 3 && gx < W-2) {
                int pos = atomicAdd(&g_cnt[b], 1);
                if (pos < CAP) {
                    g_cval[b*CAP + pos] = sT[r*WP + cb + j];
                    g_cidx[b*CAP + pos] = gy*W + gx;
                }
            }
        }
    }
}

// ============================================================================
// per-batch top-500: 3-level radix threshold + rank placement; re-zeroes g_cnt
// Scans vectorized with float4/int4.
// ============================================================================
__global__ __launch_bounds__(1024) void select_kernel() {
    __shared__ unsigned hist[2048];
    __shared__ unsigned gsum[64];
    __shared__ unsigned sel_key[1024];
    __shared__ int      sel_idx[1024];
    __shared__ int s_bsel, s_need, s_cnt;

    int b = blockIdx.x, tid = threadIdx.x;
    int lane = tid & 31, wid = tid >> 5;
    int n = min(g_cnt[b], CAP);
    __syncthreads();                     // all reads of g_cnt[b] complete ...
    if (tid == 0) g_cnt[b] = 0;          // ... before the reset (replay-safe)
    const float* vals = g_cval + b*CAP;
    const int*   idxs = g_cidx + b*CAP;
    const uint4* v4 = (const uint4*)vals;
    const int4*  i4 = (const int4*)idxs;
    int n4 = n >> 2;

    unsigned prefix = 0;
    int need = TOPK;
    for (int level = 0; level < 3; level++) {
        int nbins = (level == 2) ? 1024 : 2048;
        for (int i = tid; i < nbins; i += 1024) hist[i] = 0;
        __syncthreads();
#define HPROC(key)                                                            \
        {                                                                     \
            unsigned bin; bool ok;                                            \
            if (level == 0)      { ok = true;                  bin = (key) >> 21; }           \
            else if (level == 1) { ok = ((key) >> 21) == prefix; bin = ((key) >> 10) & 0x7FF; } \
            else                 { ok = ((key) >> 10) == prefix; bin = (key) & 0x3FF; }       \
            if (ok) atomicAdd(&hist[bin], 1);                                 \
        }
        for (int i = tid; i < n4; i += 1024) {
            uint4 q = v4[i];
            HPROC(q.x) HPROC(q.y) HPROC(q.z) HPROC(q.w)
        }
        for (int i = (n4 << 2) + tid; i < n; i += 1024) {
            unsigned key = __float_as_uint(vals[i]);
            HPROC(key)
        }
#undef HPROC
        __syncthreads();
        {
            unsigned v = hist[tid];
            #pragma unroll
            for (int o = 16; o > 0; o >>= 1) v += __shfl_down_sync(~0u, v, o);
            if (lane == 0) gsum[wid] = v;
            if (nbins == 2048) {
                unsigned v2 = hist[tid + 1024];
                #pragma unroll
                for (int o = 16; o > 0; o >>= 1) v2 += __shfl_down_sync(~0u, v2, o);
                if (lane == 0) gsum[32 + wid] = v2;
            }
        }
        __syncthreads();
        if (wid == 0) {
            int ng = nbins >> 5;
            unsigned g0 = gsum[lane];
            unsigned g1 = (ng == 64) ? gsum[32 + lane] : 0u;
            unsigned s1 = g1;
            #pragma unroll
            for (int o = 1; o < 32; o <<= 1) { unsigned t = __shfl_down_sync(~0u, s1, o); if (lane + o < 32) s1 += t; }
            unsigned tot1 = __shfl_sync(~0u, s1, 0);
            unsigned s0 = g0;
            #pragma unroll
            for (int o = 1; o < 32; o <<= 1) { unsigned t = __shfl_down_sync(~0u, s0, o); if (lane + o < 32) s0 += t; }
            s0 += tot1;
            unsigned b0 = __ballot_sync(~0u, s0 >= (unsigned)need);
            unsigned b1 = __ballot_sync(~0u, (ng == 64) && (s1 >= (unsigned)need));
            int gstar; unsigned suf_after;
            if (b1) {
                int j = 31 - __clz(b1);
                gstar = 32 + j;
                suf_after = (j == 31) ? 0u : __shfl_sync(~0u, s1, j + 1);
            } else {
                gstar = 31 - __clz(b0);
                suf_after = (gstar == 31) ? tot1 : __shfl_sync(~0u, s0, gstar + 1);
            }
            int need_g = need - (int)suf_after;
            unsigned hs = hist[gstar*32 + lane];
            #pragma unroll
            for (int o = 1; o < 32; o <<= 1) { unsigned t = __shfl_down_sync(~0u, hs, o); if (lane + o < 32) hs += t; }
            unsigned bb = __ballot_sync(~0u, hs >= (unsigned)need_g);
            int bstar = 31 - __clz(bb);
            unsigned bsuf = (bstar == 31) ? 0u : __shfl_sync(~0u, hs, bstar + 1);
            if (lane == 0) { s_bsel = gstar*32 + bstar; s_need = need_g - (int)bsuf; }
        }
        __syncthreads();
        if (level == 0)      prefix = (unsigned)s_bsel;
        else if (level == 1) prefix = (prefix << 11) | (unsigned)s_bsel;
        else                 prefix = (prefix << 10) | (unsigned)s_bsel;
        need = s_need;
        __syncthreads();
    }
    unsigned T = prefix;

    if (tid == 0) s_cnt = 0;
    __syncthreads();
#define CPROC(key, idx)                                                       \
    if ((key) >= T) {                                                         \
        int p = atomicAdd(&s_cnt, 1);                                         \
        if (p < 1024) { sel_key[p] = (key); sel_idx[p] = (idx); }             \
    }
    for (int i = tid; i < n4; i += 1024) {
        uint4 q = v4[i];
        int4  x = i4[i];
        CPROC(q.x, x.x) CPROC(q.y, x.y) CPROC(q.z, x.z) CPROC(q.w, x.w)
    }
    for (int i = (n4 << 2) + tid; i < n; i += 1024) {
        unsigned key = __float_as_uint(vals[i]);
        CPROC(key, idxs[i])
    }
#undef CPROC
    __syncthreads();
    int cnt = min(s_cnt, 1024);
    if (tid < cnt) {
        unsigned ki = sel_key[tid];
        int ii = sel_idx[tid];
        int rank = 0;
        for (int j = 0; j < cnt; j++) {
            unsigned kj = sel_key[j];
            int ij = sel_idx[j];
            rank += (kj > ki) || (kj == ki && ij < ii);
        }
        if (rank < TOPK) g_topk[b*TOPK + rank] = ii;
    }
}

__device__ __forceinline__ float wmax(float v) {
    #pragma unroll
    for (int o = 16; o > 0; o >>= 1) v = fmaxf(v, __shfl_xor_sync(0xffffffffu, v, o));
    return v;
}

// ============================================================================
// fused patch refinement + descriptor sampling: 8 keypoints per 256-thr block.
// Phase 1: all 8 warps active (1 kp each). Phase 2: 2 items/thread -> 8
// independent DRAM gathers in flight per thread.
// ============================================================================
__global__ __launch_bounds__(256) void patch_desc_kernel(
        const float* __restrict__ s, const float* __restrict__ dmap,
        float* __restrict__ out) {
    __shared__ float spx[8], spy[8];
    __shared__ float part[16];
    int tid = threadIdx.x;
    int kbase = blockIdx.x * 8;
    int wid = tid >> 5, lane = tid & 31;

    // ---- phase 1: each warp refines one keypoint ----
    {
        int gw = kbase + wid;
        int b = gw / TOPK;
        int p = g_topk[gw];
        int y = p / W, x = p - y*W;
        int ky = lane / 5, kx = lane - ky*5;
        float v = -FLT_MAX;
        if (lane < 25) v = s[(size_t)b*HW + (y + ky - 2)*W + (x + kx - 2)];
        float mx = wmax(v);
        float gxk = (float)(kx - 2), gyk = (float)(ky - 2);
        float e = (lane < 25) ? __expf((v - mx) * 10.f) : 0.f;
        float s0 = e, s1 = e*gxk, s2 = e*gyk, s3 = e*(gxk*gxk + gyk*gyk);
        #pragma unroll
        for (int o = 16; o > 0; o >>= 1) {
            s0 += __shfl_xor_sync(~0u, s0, o);
            s1 += __shfl_xor_sync(~0u, s1, o);
            s2 += __shfl_xor_sync(~0u, s2, o);
            s3 += __shfl_xor_sync(~0u, s3, o);
        }
        if (lane == 0) {
            float denom = s0 + 1e-12f;
            float inv = 1.f / denom;
            float xr = s1 * inv, yr = s2 * inv;
            float disp = (s3 - 2.f*xr*s1 - 2.f*yr*s2 + (xr*xr + yr*yr)*s0) * 0.25f * inv;
            float fx = (float)x + xr, fy = (float)y + yr;
            float gx = fx / (float)(W-1) * 2.f - 1.f;
            float gy = fy / (float)(H-1) * 2.f - 1.f;
            out[KXY_OFF + gw*2 + 0] = gx;
            out[KXY_OFF + gw*2 + 1] = gy;
            out[DISP_OFF + gw] = disp;

            float px = fminf(fmaxf((gx + 1.f) * 0.5f * (float)(W-1), 0.f), (float)(W-1));
            float py = fminf(fmaxf((gy + 1.f) * 0.5f * (float)(H-1), 0.f), (float)(H-1));
            spx[wid] = px; spy[wid] = py;
            int x0 = (int)floorf(px), y0 = (int)floorf(py);
            float wx = px - (float)x0, wy = py - (float)y0;
            int x1 = min(x0 + 1, W-1), y1 = min(y0 + 1, H-1);
            const float* sb = s + (size_t)b*HW;
            float v00 = sb[y0*W + x0], v01 = sb[y0*W + x1];
            float v10 = sb[y1*W + x0], v11 = sb[y1*W + x1];
            out[KPS_OFF + gw] = v00*(1.f-wx)*(1.f-wy) + v01*wx*(1.f-wy)
                              + v10*(1.f-wx)*wy       + v11*wx*wy;
        }
    }
    __syncthreads();

    // ---- phase 2: descriptor gather + L2 norm, 2 items per thread ----
    float dres[2];
    int kls[2], cs[2];
    #pragma unroll
    for (int it = 0; it < 2; it++) {
        int item = tid + it*256;
        int kl = item >> 6;          // 0..7
        int c  = item & 63;
        int g  = kbase + kl;
        int b  = g / TOPK;
        float px = spx[kl], py = spy[kl];
        int x0 = (int)floorf(px), y0 = (int)floorf(py);
        float wx = px - (float)x0, wy = py - (float)y0;
        int x1 = min(x0 + 1, W-1), y1 = min(y0 + 1, H-1);
        const float* base = dmap + ((size_t)b*64 + c) * (size_t)HW;
        float v00 = base[y0*W + x0], v01 = base[y0*W + x1];
        float v10 = base[y1*W + x0], v11 = base[y1*W + x1];
        dres[it] = v00*(1.f-wx)*(1.f-wy) + v01*wx*(1.f-wy)
                 + v10*(1.f-wx)*wy       + v11*wx*wy;
        kls[it] = kl; cs[it] = c;
    }
    #pragma unroll
    for (int it = 0; it < 2; it++) {
        float ss = dres[it]*dres[it];
        #pragma unroll
        for (int o = 16; o > 0; o >>= 1) ss += __shfl_xor_sync(0xffffffffu, ss, o);
        if (lane == 0) part[wid + it*8] = ss;   // item-warp index = wid + it*8
    }
    __syncthreads();
    #pragma unroll
    for (int it = 0; it < 2; it++) {
        float tot = part[2*kls[it]] + part[2*kls[it] + 1];
        float nrm = fmaxf(sqrtf(tot), 1e-12f);
        out[DESC_OFF + (kbase + kls[it])*64 + cs[it]] = dres[it] / nrm;
    }
}

extern "C" void kernel_launch(void* const* d_in, const int* in_sizes, int n_in,
                              void* d_out, int out_size) {
    const float* scores = (const float*)d_in[0];
    const float* descs  = (const float*)d_in[1];
    float* out = (float*)d_out;

    nms_kernel<<<dim3(W/32, H/32, B), 256>>>(scores);
    select_kernel<<<B, 1024>>>();
    patch_desc_kernel<<<NKP/8, 256>>>(scores, descs, out);
}

// round 17
// speedup vs baseline: 1.2177x; 1.0606x over previous
#include <cuda_runtime.h>
#include <math.h>
#include <float.h>

#define B 8
#define H 480
#define W 640
#define HW (H*W)
#define TOPK 500
#define NKP (B*TOPK)
#define CAP 131072

#define KXY_OFF 0
#define DESC_OFF (NKP*2)
#define KPS_OFF (DESC_OFF + NKP*64)
#define DISP_OFF (KPS_OFF + NKP)

typedef unsigned long long ull;

// ---------------- device scratch ----------------
__device__ float g_cval[B*CAP];
__device__ int   g_cidx[B*CAP];
__device__ int   g_cnt[B];          // zero at load; re-zeroed by select (replay-safe)
__device__ int   g_topk[NKP];

// ============================================================================
// Fused NMS (R10/R15-proven 37us): 32x32 output tile, radius-10 halo ->
// 52 rows x 56 padded cols. Masks bit-packed one ull per row.
// ============================================================================
#define WP 56

__device__ __forceinline__ float4 f4max(float4 a, float4 b) {
    return make_float4(fmaxf(a.x,b.x), fmaxf(a.y,b.y), fmaxf(a.z,b.z), fmaxf(a.w,b.w));
}
__device__ __forceinline__ float fmax5(float a, float b, float c, float d, float e) {
    return fmaxf(fmaxf(fmaxf(a, b), fmaxf(c, d)), e);
}
__device__ __forceinline__ float4 mask4(float4 t, unsigned bits) {
    t.x = (bits & 1u) ? 0.f : t.x;
    t.y = (bits & 2u) ? 0.f : t.y;
    t.z = (bits & 4u) ? 0.f : t.z;
    t.w = (bits & 8u) ? 0.f : t.w;
    return t;
}

__global__ __launch_bounds__(256) void nms_kernel(const float* __restrict__ s) {
    __shared__ __align__(16) float sT[52*WP];
    __shared__ __align__(16) float TF[52*WP];
    __shared__ ull Mb[52];
    __shared__ ull SMKb[52];

    int b = blockIdx.z, tid = threadIdx.x;
    int gx0 = blockIdx.x*32 - 10, gy0 = blockIdx.y*32 - 10;
    const float* sp = s + (size_t)b*HW;

    if (tid < 52) Mb[tid] = 0ull;

    bool interior = (gx0 >= 2) && (gx0 + 54 <= W) && (gy0 >= 0) && (gy0 + 52 <= H);
    if (interior) {
        for (int i = tid; i < 52*14; i += 256) {
            int r = i / 14, c4 = (i - (i/14)*14) * 4;
            *(float4*)&sT[r*WP + c4] =
                *(const float4*)&sp[(gy0 + r)*W + gx0 + c4 - 2];
        }
    } else {
        for (int i = tid; i < 52*WP; i += 256) {
            int r = i / WP, sc = i - r*WP;
            int gy = gy0 + r, gx = gx0 + sc - 2;
            sT[i] = (gy >= 0 && gy < H && gx >= 0 && gx < W) ? sp[gy*W + gx] : 0.f;
        }
    }
    __syncthreads();

#define F4(A, r, cb)  (*(const float4*)&A[(r)*WP + (cb)])
#define F4W(A, r, cb) (*(float4*)&A[(r)*WP + (cb)])

#define HWIN(r, cb, o0, o1, o2, o3)                                           \
    float4 L = F4(TF,r,(cb)-4), Md = F4(TF,r,cb), R = F4(TF,r,(cb)+4);        \
    float o0 = fmax5(L.z, L.w, Md.x, Md.y, Md.z);                             \
    float o1 = fmax5(L.w, Md.x, Md.y, Md.z, Md.w);                            \
    float o2 = fmax5(Md.x, Md.y, Md.z, Md.w, R.x);                            \
    float o3 = fmax5(Md.y, Md.z, Md.w, R.x, R.y);

    // ---- phase 1: vpass of raw scores, rows [2,50), all 14 chunks ----
    for (int i = tid; i < 48*14; i += 256) {
        int q = i/14; int r = 2+q; int cb = 4*(i - q*14);
        float4 v = f4max(f4max(F4(sT,r-2,cb), F4(sT,r-1,cb)),
                         f4max(F4(sT,r+1,cb), F4(sT,r+2,cb)));
        F4W(TF,r,cb) = f4max(v, F4(sT,r,cb));
    }
    __syncthreads();
    // ---- phase 2: hpass -> Mb, rows [2,50), cb 4..48 ----
    for (int i = tid; i < 48*12; i += 256) {
        int q = i/12; int r = 2+q; int cb = 4 + 4*(i - q*12);
        HWIN(r, cb, o0, o1, o2, o3)
        float4 t = F4(sT,r,cb);
        unsigned m = (t.x==o0 ? 1u:0u) | (t.y==o1 ? 2u:0u)
                   | (t.z==o2 ? 4u:0u) | (t.w==o3 ? 8u:0u);
        if (m) atomicOr(&Mb[r], (ull)m << cb);
    }
    __syncthreads();

    // ---- phase 3: suppression mask rows [4,48) ----
    if (tid < 44) {
        int r = 4 + tid;
        ull v = Mb[r-2] | Mb[r-1] | Mb[r] | Mb[r+1] | Mb[r+2];
        SMKb[r] = v | (v<<1) | (v<<2) | (v>>1) | (v>>2);
    }
    __syncthreads();

    // ---- phase 4: vpass of SS (= masked sT), rows [6,46), cb 4..48 ----
    for (int i = tid; i < 40*12; i += 256) {
        int q = i/12; int r = 6+q; int cb = 4 + 4*(i - q*12);
        float4 acc = make_float4(-FLT_MAX,-FLT_MAX,-FLT_MAX,-FLT_MAX);
        #pragma unroll
        for (int dr = -2; dr <= 2; dr++) {
            int rr = r + dr;
            unsigned bits = (unsigned)((SMKb[rr] >> cb) & 0xFull);
            acc = f4max(acc, mask4(F4(sT,rr,cb), bits));
        }
        F4W(TF,r,cb) = acc;
    }
    __syncthreads();
    // ---- phase 5: hpass -> Mb |= new peaks, rows [6,46), cb 8..44 ----
    for (int i = tid; i < 40*10; i += 256) {
        int q = i/10; int r = 6+q; int cb = 8 + 4*(i - q*10);
        HWIN(r, cb, o0, o1, o2, o3)
        unsigned smk = (unsigned)((SMKb[r] >> cb) & 0xFull);
        float4 ssv = mask4(F4(sT,r,cb), smk);
        unsigned add = ((ssv.x==o0 && !(smk&1u)) ? 1u:0u)
                     | ((ssv.y==o1 && !(smk&2u)) ? 2u:0u)
                     | ((ssv.z==o2 && !(smk&4u)) ? 4u:0u)
                     | ((ssv.w==o3 && !(smk&8u)) ? 8u:0u);
        if (add) atomicOr(&Mb[r], (ull)add << cb);
    }
    __syncthreads();

    // ---- phase 6: suppression mask rows [8,44) ----
    if (tid < 36) {
        int r = 8 + tid;
        ull v = Mb[r-2] | Mb[r-1] | Mb[r] | Mb[r+1] | Mb[r+2];
        SMKb[r] = v | (v<<1) | (v<<2) | (v>>1) | (v>>2);
    }
    __syncthreads();

    // ---- phase 7: vpass of SS4, rows [10,42), cb 8..44 ----
    for (int i = tid; i < 32*10; i += 256) {
        int q = i/10; int r = 10+q; int cb = 8 + 4*(i - q*10);
        float4 acc = make_float4(-FLT_MAX,-FLT_MAX,-FLT_MAX,-FLT_MAX);
        #pragma unroll
        for (int dr = -2; dr <= 2; dr++) {
            int rr = r + dr;
            unsigned bits = (unsigned)((SMKb[rr] >> cb) & 0xFull);
            acc = f4max(acc, mask4(F4(sT,rr,cb), bits));
        }
        F4W(TF,r,cb) = acc;
    }
    __syncthreads();
    // ---- phase 8: final + border + compaction, rows [10,42), cb 12..40 ----
    for (int i = tid; i < 32*8; i += 256) {
        int q = i/8; int r = 10+q; int cb = 12 + 4*(i - q*8);
        HWIN(r, cb, o0, o1, o2, o3)
        unsigned smk = (unsigned)((SMKb[r] >> cb) & 0xFull);
        unsigned mm  = (unsigned)((Mb[r]   >> cb) & 0xFull);
        float4 ssv = mask4(F4(sT,r,cb), smk);
        unsigned fin = mm
                     | ((ssv.x==o0 && !(smk&1u)) ? 1u:0u)
                     | ((ssv.y==o1 && !(smk&2u)) ? 2u:0u)
                     | ((ssv.z==o2 && !(smk&4u)) ? 4u:0u)
                     | ((ssv.w==o3 && !(smk&8u)) ? 8u:0u);
        while (fin) {
            int j = __ffs(fin) - 1;
            fin &= fin - 1;
            int gy = gy0 + r, gx = gx0 + cb + j - 2;
            if (gy >= 3 && gy < H-2 && gx >= 3 && gx < W-2) {
                int pos = atomicAdd(&g_cnt[b], 1);
                if (pos < CAP) {
                    g_cval[b*CAP + pos] = sT[r*WP + cb + j];
                    g_cidx[b*CAP + pos] = gy*W + gx;
                }
            }
        }
    }
}

// ============================================================================
// per-batch top-500: TWO-level radix threshold (22-bit prefix) + collect +
// rank placement. Collect over-fetches only the level-1 bin population (~few).
// ============================================================================
__global__ __launch_bounds__(1024) void select_kernel() {
    __shared__ unsigned hist[2048];
    __shared__ unsigned gsum[64];
    __shared__ unsigned sel_key[1024];
    __shared__ int      sel_idx[1024];
    __shared__ int s_bsel, s_need, s_cnt;

    int b = blockIdx.x, tid = threadIdx.x;
    int lane = tid & 31, wid = tid >> 5;
    int n = min(g_cnt[b], CAP);
    __syncthreads();                     // all reads of g_cnt[b] complete ...
    if (tid == 0) g_cnt[b] = 0;          // ... before the reset (replay-safe)
    const float* vals = g_cval + b*CAP;
    const int*   idxs = g_cidx + b*CAP;
    const uint4* v4 = (const uint4*)vals;
    const int4*  i4 = (const int4*)idxs;
    int n4 = n >> 2;

    unsigned prefix = 0;
    int need = TOPK;
    #pragma unroll
    for (int level = 0; level < 2; level++) {
        for (int i = tid; i < 2048; i += 1024) hist[i] = 0;
        __syncthreads();
#define HPROC(key)                                                            \
        {                                                                     \
            unsigned bin; bool ok;                                            \
            if (level == 0) { ok = true;                    bin = (key) >> 21; } \
            else            { ok = ((key) >> 21) == prefix; bin = ((key) >> 10) & 0x7FF; } \
            if (ok) atomicAdd(&hist[bin], 1);                                 \
        }
        for (int i = tid; i < n4; i += 1024) {
            uint4 q = v4[i];
            HPROC(q.x) HPROC(q.y) HPROC(q.z) HPROC(q.w)
        }
        for (int i = (n4 << 2) + tid; i < n; i += 1024) {
            unsigned key = __float_as_uint(vals[i]);
            HPROC(key)
        }
#undef HPROC
        __syncthreads();
        {
            unsigned v = hist[tid];
            #pragma unroll
            for (int o = 16; o > 0; o >>= 1) v += __shfl_down_sync(~0u, v, o);
            if (lane == 0) gsum[wid] = v;
            unsigned v2 = hist[tid + 1024];
            #pragma unroll
            for (int o = 16; o > 0; o >>= 1) v2 += __shfl_down_sync(~0u, v2, o);
            if (lane == 0) gsum[32 + wid] = v2;
        }
        __syncthreads();
        if (wid == 0) {
            unsigned g0 = gsum[lane];
            unsigned g1 = gsum[32 + lane];
            unsigned s1 = g1;
            #pragma unroll
            for (int o = 1; o < 32; o <<= 1) { unsigned t = __shfl_down_sync(~0u, s1, o); if (lane + o < 32) s1 += t; }
            unsigned tot1 = __shfl_sync(~0u, s1, 0);
            unsigned s0 = g0;
            #pragma unroll
            for (int o = 1; o < 32; o <<= 1) { unsigned t = __shfl_down_sync(~0u, s0, o); if (lane + o < 32) s0 += t; }
            s0 += tot1;
            unsigned b0 = __ballot_sync(~0u, s0 >= (unsigned)need);
            unsigned b1 = __ballot_sync(~0u, s1 >= (unsigned)need);
            int gstar; unsigned suf_after;
            if (b1) {
                int j = 31 - __clz(b1);
                gstar = 32 + j;
                suf_after = (j == 31) ? 0u : __shfl_sync(~0u, s1, j + 1);
            } else {
                gstar = 31 - __clz(b0);
                suf_after = (gstar == 31) ? tot1 : __shfl_sync(~0u, s0, gstar + 1);
            }
            int need_g = need - (int)suf_after;
            unsigned hs = hist[gstar*32 + lane];
            #pragma unroll
            for (int o = 1; o < 32; o <<= 1) { unsigned t = __shfl_down_sync(~0u, hs, o); if (lane + o < 32) hs += t; }
            unsigned bb = __ballot_sync(~0u, hs >= (unsigned)need_g);
            int bstar = 31 - __clz(bb);
            unsigned bsuf = (bstar == 31) ? 0u : __shfl_sync(~0u, hs, bstar + 1);
            if (lane == 0) { s_bsel = gstar*32 + bstar; s_need = need_g - (int)bsuf; }
        }
        __syncthreads();
        if (level == 0) prefix = (unsigned)s_bsel;
        else            prefix = (prefix << 11) | (unsigned)s_bsel;
        need = s_need;
        __syncthreads();
    }
    unsigned T22 = prefix;   // 22-bit prefix; collect (key>>10) >= T22

    if (tid == 0) s_cnt = 0;
    __syncthreads();
#define CPROC(key, idx)                                                       \
    if (((key) >> 10) >= T22) {                                               \
        int p = atomicAdd(&s_cnt, 1);                                         \
        if (p < 1024) { sel_key[p] = (key); sel_idx[p] = (idx); }             \
    }
    for (int i = tid; i < n4; i += 1024) {
        uint4 q = v4[i];
        int4  x = i4[i];
        CPROC(q.x, x.x) CPROC(q.y, x.y) CPROC(q.z, x.z) CPROC(q.w, x.w)
    }
    for (int i = (n4 << 2) + tid; i < n; i += 1024) {
        unsigned key = __float_as_uint(vals[i]);
        CPROC(key, idxs[i])
    }
#undef CPROC
    __syncthreads();
    int cnt = min(s_cnt, 1024);
    if (tid < cnt) {
        unsigned ki = sel_key[tid];
        int ii = sel_idx[tid];
        int rank = 0;
        for (int j = 0; j < cnt; j++) {
            unsigned kj = sel_key[j];
            int ij = sel_idx[j];
            rank += (kj > ki) || (kj == ki && ij < ii);
        }
        if (rank < TOPK) g_topk[b*TOPK + rank] = ii;
    }
}

__device__ __forceinline__ float wmax(float v) {
    #pragma unroll
    for (int o = 16; o > 0; o >>= 1) v = fmaxf(v, __shfl_xor_sync(0xffffffffu, v, o));
    return v;
}

// ============================================================================
// fused patch refinement + descriptor sampling: 16 keypoints per 256-thr
// block. Phase 1: each warp refines 2 kps. Phase 2: 4 items/thread -> 16
// independent DRAM gathers in flight per thread.
// ============================================================================
__global__ __launch_bounds__(256) void patch_desc_kernel(
        const float* __restrict__ s, const float* __restrict__ dmap,
        float* __restrict__ out) {
    __shared__ float spx[16], spy[16];
    __shared__ float part[32];
    int tid = threadIdx.x;
    int kbase = blockIdx.x * 16;
    int wid = tid >> 5, lane = tid & 31;

    // ---- phase 1: each warp refines 2 keypoints ----
    #pragma unroll
    for (int kk = 0; kk < 2; kk++) {
        int kl = wid + kk*8;
        int gw = kbase + kl;
        int b = gw / TOPK;
        int p = g_topk[gw];
        int y = p / W, x = p - y*W;
        int ky = lane / 5, kx = lane - ky*5;
        float v = -FLT_MAX;
        if (lane < 25) v = s[(size_t)b*HW + (y + ky - 2)*W + (x + kx - 2)];
        float mx = wmax(v);
        float gxk = (float)(kx - 2), gyk = (float)(ky - 2);
        float e = (lane < 25) ? __expf((v - mx) * 10.f) : 0.f;
        float s0 = e, s1 = e*gxk, s2 = e*gyk, s3 = e*(gxk*gxk + gyk*gyk);
        #pragma unroll
        for (int o = 16; o > 0; o >>= 1) {
            s0 += __shfl_xor_sync(~0u, s0, o);
            s1 += __shfl_xor_sync(~0u, s1, o);
            s2 += __shfl_xor_sync(~0u, s2, o);
            s3 += __shfl_xor_sync(~0u, s3, o);
        }
        if (lane == 0) {
            float denom = s0 + 1e-12f;
            float inv = 1.f / denom;
            float xr = s1 * inv, yr = s2 * inv;
            float disp = (s3 - 2.f*xr*s1 - 2.f*yr*s2 + (xr*xr + yr*yr)*s0) * 0.25f * inv;
            float fx = (float)x + xr, fy = (float)y + yr;
            float gx = fx / (float)(W-1) * 2.f - 1.f;
            float gy = fy / (float)(H-1) * 2.f - 1.f;
            out[KXY_OFF + gw*2 + 0] = gx;
            out[KXY_OFF + gw*2 + 1] = gy;
            out[DISP_OFF + gw] = disp;

            float px = fminf(fmaxf((gx + 1.f) * 0.5f * (float)(W-1), 0.f), (float)(W-1));
            float py = fminf(fmaxf((gy + 1.f) * 0.5f * (float)(H-1), 0.f), (float)(H-1));
            spx[kl] = px; spy[kl] = py;
            int x0 = (int)floorf(px), y0 = (int)floorf(py);
            float wx = px - (float)x0, wy = py - (float)y0;
            int x1 = min(x0 + 1, W-1), y1 = min(y0 + 1, H-1);
            const float* sb = s + (size_t)b*HW;
            float v00 = sb[y0*W + x0], v01 = sb[y0*W + x1];
            float v10 = sb[y1*W + x0], v11 = sb[y1*W + x1];
            out[KPS_OFF + gw] = v00*(1.f-wx)*(1.f-wy) + v01*wx*(1.f-wy)
                              + v10*(1.f-wx)*wy       + v11*wx*wy;
        }
    }
    __syncthreads();

    // ---- phase 2: descriptor gather + L2 norm, 4 items per thread ----
    float dres[4];
    int kls[4], cs[4];
    #pragma unroll
    for (int it = 0; it < 4; it++) {
        int item = tid + it*256;
        int kl = item >> 6;          // 0..15
        int c  = item & 63;
        int g  = kbase + kl;
        int b  = g / TOPK;
        float px = spx[kl], py = spy[kl];
        int x0 = (int)floorf(px), y0 = (int)floorf(py);
        float wx = px - (float)x0, wy = py - (float)y0;
        int x1 = min(x0 + 1, W-1), y1 = min(y0 + 1, H-1);
        const float* base = dmap + ((size_t)b*64 + c) * (size_t)HW;
        float v00 = base[y0*W + x0], v01 = base[y0*W + x1];
        float v10 = base[y1*W + x0], v11 = base[y1*W + x1];
        dres[it] = v00*(1.f-wx)*(1.f-wy) + v01*wx*(1.f-wy)
                 + v10*(1.f-wx)*wy       + v11*wx*wy;
        kls[it] = kl; cs[it] = c;
    }
    #pragma unroll
    for (int it = 0; it < 4; it++) {
        float ss = dres[it]*dres[it];
        #pragma unroll
        for (int o = 16; o > 0; o >>= 1) ss += __shfl_xor_sync(0xffffffffu, ss, o);
        if (lane == 0) part[wid + it*8] = ss;   // item warp index = it*8 + wid
    }
    __syncthreads();
    #pragma unroll
    for (int it = 0; it < 4; it++) {
        float tot = part[2*kls[it]] + part[2*kls[it] + 1];
        float nrm = fmaxf(sqrtf(tot), 1e-12f);
        out[DESC_OFF + (kbase + kls[it])*64 + cs[it]] = dres[it] / nrm;
    }
}

extern "C" void kernel_launch(void* const* d_in, const int* in_sizes, int n_in,
                              void* d_out, int out_size) {
    const float* scores = (const float*)d_in[0];
    const float* descs  = (const float*)d_in[1];
    float* out = (float*)d_out;

    nms_kernel<<<dim3(W/32, H/32, B), 256>>>(scores);
    select_kernel<<<B, 1024>>>();
    patch_desc_kernel<<<NKP/16, 256>>>(scores, descs, out);
}